// round 14
// baseline (speedup 1.0000x reference)
#include <cuda_runtime.h>
#include <cuda_bf16.h>
#include <cstdint>

#define BB     256
#define IN_F   1024
#define OUT_F  128
#define KD     16
#define NCOL   (OUT_F * KD)        // 2048
#define OUTW   (IN_F + OUT_F)      // 1152

#define SPLITS 4
#define KSPLIT (IN_F / SPLITS)     // 256
#define PSZ    (BB * NCOL)         // 524288
#define BM     64
#define BN     64
#define BKK    32
#define NKT    (KSPLIT / BKK)      // 8
#define STAGES 3

#define A_STRIDE 80                // bytes/row: 32 bf16 + pad
#define B_STRIDE 144               // bytes/row: 64 bf16 + pad

#define QSPLIT 8                   // pair t-range slices

// exp(-s) == +0.0f exactly for s >= 105; partial L1 sums are lower bounds,
// so screening on partial >= THRESH is lossless.
#define THRESH 105.0f

__device__ float d_part[SPLITS * PSZ];           // [sp][o][b][k] fp32, 8 MB
__device__ float d_m2[PSZ];                      // reduced m, 2 MB
__device__ __nv_bfloat16 d_tb[IN_F * NCOL];      // t in bf16, 4 MB
__device__ __nv_bfloat16 d_xb[BB * IN_F];        // x in bf16, 0.5 MB

__device__ __forceinline__ unsigned long long addx2(unsigned long long a,
                                                    unsigned long long b) {
    unsigned long long r;
    asm("add.rn.f32x2 %0, %1, %2;" : "=l"(r) : "l"(a), "l"(b));
    return r;
}

__device__ __forceinline__ void cp16(uint32_t smem, const void* gmem) {
    asm volatile("cp.async.cg.shared.global [%0], [%1], 16;"
                 :: "r"(smem), "l"(gmem));
}

__device__ __forceinline__ void ldmat4(uint32_t& r0, uint32_t& r1,
                                       uint32_t& r2, uint32_t& r3,
                                       uint32_t addr) {
    asm volatile("ldmatrix.sync.aligned.m8n8.x4.shared.b16 {%0,%1,%2,%3}, [%4];"
                 : "=r"(r0), "=r"(r1), "=r"(r2), "=r"(r3) : "r"(addr));
}
__device__ __forceinline__ void ldmat4t(uint32_t& r0, uint32_t& r1,
                                        uint32_t& r2, uint32_t& r3,
                                        uint32_t addr) {
    asm volatile("ldmatrix.sync.aligned.m8n8.x4.trans.shared.b16 {%0,%1,%2,%3}, [%4];"
                 : "=r"(r0), "=r"(r1), "=r"(r2), "=r"(r3) : "r"(addr));
}

// ---------------------------------------------------------------------------
// Convert t,x -> bf16 + x passthrough + o_b zero init.
// grid 1280: [0,1024) t-convert, [1024,1152) x-convert, [1152,1280) copy/init.
// ---------------------------------------------------------------------------
__global__ __launch_bounds__(256) void conv_kernel(
    const float* __restrict__ t, const float* __restrict__ x,
    __nv_bfloat16* __restrict__ tb, __nv_bfloat16* __restrict__ xb,
    float* __restrict__ out)
{
    const int tid = threadIdx.x;
    const int blk = blockIdx.x;

    if (blk < 1024 + 128) {
        const float*   src = (blk < 1024) ? t : x;
        __nv_bfloat16* dst = (blk < 1024) ? tb : xb;
        const size_t gid = (size_t)(blk < 1024 ? blk : blk - 1024) * 256 + tid;
        const float4* s4 = (const float4*)src;
        float4 v0 = s4[gid * 2];
        float4 v1 = s4[gid * 2 + 1];
        __nv_bfloat162 b0 = __floats2bfloat162_rn(v0.x, v0.y);
        __nv_bfloat162 b1 = __floats2bfloat162_rn(v0.z, v0.w);
        __nv_bfloat162 b2 = __floats2bfloat162_rn(v1.x, v1.y);
        __nv_bfloat162 b3 = __floats2bfloat162_rn(v1.z, v1.w);
        uint4 o;
        o.x = *(uint32_t*)&b0; o.y = *(uint32_t*)&b1;
        o.z = *(uint32_t*)&b2; o.w = *(uint32_t*)&b3;
        *(uint4*)&dst[gid * 8] = o;
        return;
    }

    const int id = blk - 1152;
    const int r  = id * 2 + (tid >> 7);
    const int j  = tid & 127;
    const float4* src = (const float4*)(x + r * IN_F);
    float4*       dst = (float4*)(out + r * OUTW);
    dst[j]       = src[j];
    dst[j + 128] = src[j + 128];
    if (j < 32)   // diagonal never computed -> 0
        ((float4*)(out + r * OUTW + IN_F))[j] = make_float4(0.f, 0.f, 0.f, 0.f);
}

// ---------------------------------------------------------------------------
// GEMM via mma.sync m16n8k16 bf16: split-K x4, 64x64 tiles, 128 threads
// (4 warps, 32x32 warp tiles), ldmatrix, 3-stage cp.async ring, one barrier
// per iter. grid (32,4,4). Transposed epilogue [o][b][k].
// ---------------------------------------------------------------------------
__global__ __launch_bounds__(128) void gemm_bf16_kernel(
    const __nv_bfloat16* __restrict__ A,   // xb [256][1024]
    const __nv_bfloat16* __restrict__ B,   // tb [1024][2048]
    float* __restrict__ C)                  // d_part
{
    __shared__ char As[STAGES][BM * A_STRIDE];
    __shared__ char Bs[STAGES][BKK * B_STRIDE];

    const int tid  = threadIdx.x;
    const int lane = tid & 31;
    const int wid  = tid >> 5;
    const int g    = lane >> 2;
    const int t    = lane & 3;
    const int wm   = (wid >> 1) * 32;
    const int wn   = (wid & 1) * 32;
    const int bm0  = blockIdx.y * BM;
    const int bn0  = blockIdx.x * BN;
    const int koff = blockIdx.z * KSPLIT;

    const int lm = lane & 15;
    const int lh = (lane >> 4) & 1;

    const int arow = tid >> 2;
    const int ach  = tid & 3;
    const int brow = tid >> 3;
    const int bch  = tid & 7;

    uint32_t as_b[STAGES], bs_b[STAGES];
#pragma unroll
    for (int b = 0; b < STAGES; b++) {
        as_b[b] = (uint32_t)__cvta_generic_to_shared(&As[b][0]);
        bs_b[b] = (uint32_t)__cvta_generic_to_shared(&Bs[b][0]);
    }

    auto fetch = [&](int buf, int k0) {
#pragma unroll
        for (int i = 0; i < 2; i++) {
            const int r = arow + i * 32;
            cp16(as_b[buf] + r * A_STRIDE + ach * 16,
                 &A[(size_t)(bm0 + r) * IN_F + k0 + ach * 8]);
        }
#pragma unroll
        for (int i = 0; i < 2; i++) {
            const int r = brow + i * 16;
            cp16(bs_b[buf] + r * B_STRIDE + bch * 16,
                 &B[(size_t)(k0 + r) * NCOL + bn0 + bch * 8]);
        }
        asm volatile("cp.async.commit_group;");
    };

    float acc[2][4][4];
#pragma unroll
    for (int mf = 0; mf < 2; mf++)
#pragma unroll
        for (int nf = 0; nf < 4; nf++)
#pragma unroll
            for (int i = 0; i < 4; i++) acc[mf][nf][i] = 0.0f;

    fetch(0, koff);
    fetch(1, koff + BKK);

#pragma unroll 1
    for (int kt = 0; kt < NKT; kt++) {
        if (kt + 1 < NKT) asm volatile("cp.async.wait_group 1;");
        else              asm volatile("cp.async.wait_group 0;");
        __syncthreads();

        if (kt + 2 < NKT) fetch((kt + 2) % STAGES, koff + (kt + 2) * BKK);

        const int cur = kt % STAGES;
#pragma unroll
        for (int ks = 0; ks < 2; ks++) {
            uint32_t ua[2][4], ub[4][2];
#pragma unroll
            for (int mf = 0; mf < 2; mf++) {
                uint32_t addr = as_b[cur] + (wm + mf * 16 + lm) * A_STRIDE
                              + ks * 32 + lh * 16;
                ldmat4(ua[mf][0], ua[mf][1], ua[mf][2], ua[mf][3], addr);
            }
#pragma unroll
            for (int p = 0; p < 2; p++) {
                uint32_t addr = bs_b[cur] + (ks * 16 + lm) * B_STRIDE
                              + (wn + p * 16) * 2 + lh * 16;
                ldmat4t(ub[2 * p][0], ub[2 * p][1],
                        ub[2 * p + 1][0], ub[2 * p + 1][1], addr);
            }
#pragma unroll
            for (int mf = 0; mf < 2; mf++)
#pragma unroll
                for (int nf = 0; nf < 4; nf++) {
                    asm volatile(
                        "mma.sync.aligned.m16n8k16.row.col.f32.bf16.bf16.f32 "
                        "{%0,%1,%2,%3}, {%4,%5,%6,%7}, {%8,%9}, {%0,%1,%2,%3};\n"
                        : "+f"(acc[mf][nf][0]), "+f"(acc[mf][nf][1]),
                          "+f"(acc[mf][nf][2]), "+f"(acc[mf][nf][3])
                        : "r"(ua[mf][0]), "r"(ua[mf][1]),
                          "r"(ua[mf][2]), "r"(ua[mf][3]),
                          "r"(ub[nf][0]), "r"(ub[nf][1]));
                }
        }
    }

    float* Cz = C + blockIdx.z * PSZ;
#pragma unroll
    for (int mf = 0; mf < 2; mf++)
#pragma unroll
        for (int nf = 0; nf < 4; nf++) {
            const int r0 = bm0 + wm + mf * 16 + g;
            const int o  = ((bn0 + wn) >> 4) + (nf >> 1);
            const int k  = ((nf & 1) << 3) + t * 2;
            float* p = Cz + o * (BB * KD) + k;
            *(float2*)&p[r0 * KD] =
                make_float2(acc[mf][nf][0], acc[mf][nf][1]);
            *(float2*)&p[(r0 + 8) * KD] =
                make_float2(acc[mf][nf][2], acc[mf][nf][3]);
        }
}

// ---------------------------------------------------------------------------
// Reduce split-K partials: m = sum_sp part[sp]. Fully coalesced float4.
// ---------------------------------------------------------------------------
__global__ __launch_bounds__(256) void reduce_kernel(
    const float* __restrict__ part, float* __restrict__ m)
{
    const int idx = blockIdx.x * 256 + threadIdx.x;
    const float4* p = (const float4*)part;
    float4 acc = p[idx];
#pragma unroll
    for (int sp = 1; sp < SPLITS; sp++) {
        float4 v = p[idx + sp * (PSZ / 4)];
        acc.x += v.x; acc.y += v.y; acc.z += v.z; acc.w += v.w;
    }
    ((float4*)m)[idx] = acc;
}

// ---------------------------------------------------------------------------
// Pairwise exp(-L1), balanced cyclic triangle, 8 t-slices.
// grid (128 o, 8 slice), 256 threads; 16 iters/thread (s7: 15+peel).
// ---------------------------------------------------------------------------
__global__ __launch_bounds__(256) void pair_kernel(
    const float* __restrict__ m, float* __restrict__ out)
{
    __shared__ ulonglong2 sm2[4][BB];   // [chunk][b], negated rows, 16 KB

    const int o   = blockIdx.x;
    const int s   = blockIdx.y;
    const int b1  = threadIdx.x;
    const unsigned long long SGN = 0x8000000080000000ULL;

    const ulonglong2* mo = (const ulonglong2*)(m + (size_t)o * (BB * KD));
#pragma unroll
    for (int i = 0; i < 4; i++) {
        const int f = b1 + (i << 8);
        ulonglong2 v = mo[f];
        v.x ^= SGN; v.y ^= SGN;
        sm2[f & 3][f >> 2] = v;
    }
    __syncthreads();

    unsigned long long a[8];
#pragma unroll
    for (int i = 0; i < 4; i++) {
        ulonglong2 v = sm2[i][b1];
        a[2 * i]     = v.x ^ SGN;
        a[2 * i + 1] = v.y ^ SGN;
    }

    const unsigned long long MSK = 0x7FFFFFFF7FFFFFFFULL;
    float* ob = out + IN_F + o;
    float tot = 0.0f;

    auto body = [&](int t) {
        const int b2 = (b1 + t) & 255;
        ulonglong2 c0 = sm2[0][b2], c1 = sm2[1][b2];
        unsigned long long d0 = addx2(a[0], c0.x) & MSK;
        unsigned long long d1 = addx2(a[1], c0.y) & MSK;
        unsigned long long d2 = addx2(a[2], c1.x) & MSK;
        unsigned long long d3 = addx2(a[3], c1.y) & MSK;
        unsigned long long f  = addx2(addx2(d0, d1), addx2(d2, d3));
        uint32_t flo, fhi;
        asm("mov.b64 {%0,%1}, %2;" : "=r"(flo), "=r"(fhi) : "l"(f));
        float s8 = __uint_as_float(flo) + __uint_as_float(fhi);

        if (s8 < THRESH) {
            ulonglong2 c2 = sm2[2][b2], c3 = sm2[3][b2];
            unsigned long long d4 = addx2(a[4], c2.x) & MSK;
            unsigned long long d5 = addx2(a[5], c2.y) & MSK;
            unsigned long long d6 = addx2(a[6], c3.x) & MSK;
            unsigned long long d7 = addx2(a[7], c3.y) & MSK;
            unsigned long long g  = addx2(addx2(d4, d5), addx2(d6, d7));
            uint32_t glo, ghi;
            asm("mov.b64 {%0,%1}, %2;" : "=r"(glo), "=r"(ghi) : "l"(g));
            float s16 = s8 + __uint_as_float(glo) + __uint_as_float(ghi);
            float e = __expf(-s16);
            tot += e;
            if (e != 0.0f)
                atomicAdd(&ob[(size_t)b2 * OUTW], e);
        }
    };

    // slices: t = 1+16s .. 16+16s  (s=7: ..127, then peel t=128 once)
    const int t0   = 1 + (s << 4);
    const int tend = (s == QSPLIT - 1) ? 128 : t0 + 16;
#pragma unroll 4
    for (int t = t0; t < tend; t++) body(t);
    if (s == QSPLIT - 1 && b1 < 128) body(128);

    if (tot != 0.0f)
        atomicAdd(&ob[(size_t)b1 * OUTW], tot);
}

extern "C" void kernel_launch(void* const* d_in, const int* in_sizes, int n_in,
                              void* d_out, int out_size)
{
    const float* x = (const float*)d_in[0];     // [256][1024]
    const float* t = (const float*)d_in[1];     // [1024][2048]
    float* out = (float*)d_out;                 // [256][1152]

    float* part;          cudaGetSymbolAddress((void**)&part, d_part);
    float* m;             cudaGetSymbolAddress((void**)&m, d_m2);
    __nv_bfloat16* tb;    cudaGetSymbolAddress((void**)&tb, d_tb);
    __nv_bfloat16* xb;    cudaGetSymbolAddress((void**)&xb, d_xb);

    conv_kernel<<<1280, 256>>>(t, x, tb, xb, out);
    dim3 ggrid(NCOL / BN, BB / BM, SPLITS);      // (32, 4, 4)
    gemm_bf16_kernel<<<ggrid, 128>>>(xb, tb, part);
    reduce_kernel<<<PSZ / 4 / 256, 256>>>(part, m);
    pair_kernel<<<dim3(OUT_F, QSPLIT), 256>>>(m, out);
}

// round 15
// speedup vs baseline: 1.0784x; 1.0784x over previous
#include <cuda_runtime.h>
#include <cuda_bf16.h>
#include <cstdint>

#define BB     256
#define IN_F   1024
#define OUT_F  128
#define KD     16
#define NCOL   (OUT_F * KD)        // 2048
#define OUTW   (IN_F + OUT_F)      // 1152

#define SPLITS 4
#define KSPLIT (IN_F / SPLITS)     // 256
#define PSZ    (BB * NCOL)         // 524288
#define BM     64
#define BN     64
#define BKK    32
#define NKT    (KSPLIT / BKK)      // 8
#define STAGES 3

#define A_STRIDE 80
#define B_STRIDE 144

#define QSPLIT 4                   // pair t-range slices

// exp(-s) == +0.0f exactly for s >= 105 (with bf16 slack: true cutoff 104);
// partial L1 sums are lower bounds, so screening is lossless.
#define THRESH 105.0f

__device__ float d_part[SPLITS * PSZ];           // [sp][o][b][k] fp32, 8 MB
__device__ __nv_bfloat16 d_mb[PSZ];              // reduced m, bf16, 1 MB
__device__ __nv_bfloat16 d_tb[IN_F * NCOL];      // t in bf16, 4 MB
__device__ __nv_bfloat16 d_xb[BB * IN_F];        // x in bf16, 0.5 MB

__device__ __forceinline__ void cp16(uint32_t smem, const void* gmem) {
    asm volatile("cp.async.cg.shared.global [%0], [%1], 16;"
                 :: "r"(smem), "l"(gmem));
}

__device__ __forceinline__ uint32_t hadd2(uint32_t a, uint32_t b) {
    uint32_t r;
    asm("add.rn.bf16x2 %0, %1, %2;" : "=r"(r) : "r"(a), "r"(b));
    return r;
}

__device__ __forceinline__ void ldmat4(uint32_t& r0, uint32_t& r1,
                                       uint32_t& r2, uint32_t& r3,
                                       uint32_t addr) {
    asm volatile("ldmatrix.sync.aligned.m8n8.x4.shared.b16 {%0,%1,%2,%3}, [%4];"
                 : "=r"(r0), "=r"(r1), "=r"(r2), "=r"(r3) : "r"(addr));
}
__device__ __forceinline__ void ldmat4t(uint32_t& r0, uint32_t& r1,
                                        uint32_t& r2, uint32_t& r3,
                                        uint32_t addr) {
    asm volatile("ldmatrix.sync.aligned.m8n8.x4.trans.shared.b16 {%0,%1,%2,%3}, [%4];"
                 : "=r"(r0), "=r"(r1), "=r"(r2), "=r"(r3) : "r"(addr));
}

// ---------------------------------------------------------------------------
// Convert t,x -> bf16 + x passthrough + o_b zero init.
// ---------------------------------------------------------------------------
__global__ __launch_bounds__(256) void conv_kernel(
    const float* __restrict__ t, const float* __restrict__ x,
    __nv_bfloat16* __restrict__ tb, __nv_bfloat16* __restrict__ xb,
    float* __restrict__ out)
{
    const int tid = threadIdx.x;
    const int blk = blockIdx.x;

    if (blk < 1024 + 128) {
        const float*   src = (blk < 1024) ? t : x;
        __nv_bfloat16* dst = (blk < 1024) ? tb : xb;
        const size_t gid = (size_t)(blk < 1024 ? blk : blk - 1024) * 256 + tid;
        const float4* s4 = (const float4*)src;
        float4 v0 = s4[gid * 2];
        float4 v1 = s4[gid * 2 + 1];
        __nv_bfloat162 b0 = __floats2bfloat162_rn(v0.x, v0.y);
        __nv_bfloat162 b1 = __floats2bfloat162_rn(v0.z, v0.w);
        __nv_bfloat162 b2 = __floats2bfloat162_rn(v1.x, v1.y);
        __nv_bfloat162 b3 = __floats2bfloat162_rn(v1.z, v1.w);
        uint4 o;
        o.x = *(uint32_t*)&b0; o.y = *(uint32_t*)&b1;
        o.z = *(uint32_t*)&b2; o.w = *(uint32_t*)&b3;
        *(uint4*)&dst[gid * 8] = o;
        return;
    }

    const int id = blk - 1152;
    const int r  = id * 2 + (tid >> 7);
    const int j  = tid & 127;
    const float4* src = (const float4*)(x + r * IN_F);
    float4*       dst = (float4*)(out + r * OUTW);
    dst[j]       = src[j];
    dst[j + 128] = src[j + 128];
    if (j < 32)   // diagonal never computed -> 0
        ((float4*)(out + r * OUTW + IN_F))[j] = make_float4(0.f, 0.f, 0.f, 0.f);
}

// ---------------------------------------------------------------------------
// GEMM via mma.sync m16n8k16 bf16 (unchanged from R13).
// ---------------------------------------------------------------------------
__global__ __launch_bounds__(128) void gemm_bf16_kernel(
    const __nv_bfloat16* __restrict__ A,
    const __nv_bfloat16* __restrict__ B,
    float* __restrict__ C)
{
    __shared__ char As[STAGES][BM * A_STRIDE];
    __shared__ char Bs[STAGES][BKK * B_STRIDE];

    const int tid  = threadIdx.x;
    const int lane = tid & 31;
    const int wid  = tid >> 5;
    const int g    = lane >> 2;
    const int t    = lane & 3;
    const int wm   = (wid >> 1) * 32;
    const int wn   = (wid & 1) * 32;
    const int bm0  = blockIdx.y * BM;
    const int bn0  = blockIdx.x * BN;
    const int koff = blockIdx.z * KSPLIT;

    const int lm = lane & 15;
    const int lh = (lane >> 4) & 1;

    const int arow = tid >> 2;
    const int ach  = tid & 3;
    const int brow = tid >> 3;
    const int bch  = tid & 7;

    uint32_t as_b[STAGES], bs_b[STAGES];
#pragma unroll
    for (int b = 0; b < STAGES; b++) {
        as_b[b] = (uint32_t)__cvta_generic_to_shared(&As[b][0]);
        bs_b[b] = (uint32_t)__cvta_generic_to_shared(&Bs[b][0]);
    }

    auto fetch = [&](int buf, int k0) {
#pragma unroll
        for (int i = 0; i < 2; i++) {
            const int r = arow + i * 32;
            cp16(as_b[buf] + r * A_STRIDE + ach * 16,
                 &A[(size_t)(bm0 + r) * IN_F + k0 + ach * 8]);
        }
#pragma unroll
        for (int i = 0; i < 2; i++) {
            const int r = brow + i * 16;
            cp16(bs_b[buf] + r * B_STRIDE + bch * 16,
                 &B[(size_t)(k0 + r) * NCOL + bn0 + bch * 8]);
        }
        asm volatile("cp.async.commit_group;");
    };

    float acc[2][4][4];
#pragma unroll
    for (int mf = 0; mf < 2; mf++)
#pragma unroll
        for (int nf = 0; nf < 4; nf++)
#pragma unroll
            for (int i = 0; i < 4; i++) acc[mf][nf][i] = 0.0f;

    fetch(0, koff);
    fetch(1, koff + BKK);

#pragma unroll 1
    for (int kt = 0; kt < NKT; kt++) {
        if (kt + 1 < NKT) asm volatile("cp.async.wait_group 1;");
        else              asm volatile("cp.async.wait_group 0;");
        __syncthreads();

        if (kt + 2 < NKT) fetch((kt + 2) % STAGES, koff + (kt + 2) * BKK);

        const int cur = kt % STAGES;
#pragma unroll
        for (int ks = 0; ks < 2; ks++) {
            uint32_t ua[2][4], ub[4][2];
#pragma unroll
            for (int mf = 0; mf < 2; mf++) {
                uint32_t addr = as_b[cur] + (wm + mf * 16 + lm) * A_STRIDE
                              + ks * 32 + lh * 16;
                ldmat4(ua[mf][0], ua[mf][1], ua[mf][2], ua[mf][3], addr);
            }
#pragma unroll
            for (int p = 0; p < 2; p++) {
                uint32_t addr = bs_b[cur] + (ks * 16 + lm) * B_STRIDE
                              + (wn + p * 16) * 2 + lh * 16;
                ldmat4t(ub[2 * p][0], ub[2 * p][1],
                        ub[2 * p + 1][0], ub[2 * p + 1][1], addr);
            }
#pragma unroll
            for (int mf = 0; mf < 2; mf++)
#pragma unroll
                for (int nf = 0; nf < 4; nf++) {
                    asm volatile(
                        "mma.sync.aligned.m16n8k16.row.col.f32.bf16.bf16.f32 "
                        "{%0,%1,%2,%3}, {%4,%5,%6,%7}, {%8,%9}, {%0,%1,%2,%3};\n"
                        : "+f"(acc[mf][nf][0]), "+f"(acc[mf][nf][1]),
                          "+f"(acc[mf][nf][2]), "+f"(acc[mf][nf][3])
                        : "r"(ua[mf][0]), "r"(ua[mf][1]),
                          "r"(ua[mf][2]), "r"(ua[mf][3]),
                          "r"(ub[nf][0]), "r"(ub[nf][1]));
                }
        }
    }

    float* Cz = C + blockIdx.z * PSZ;
#pragma unroll
    for (int mf = 0; mf < 2; mf++)
#pragma unroll
        for (int nf = 0; nf < 4; nf++) {
            const int r0 = bm0 + wm + mf * 16 + g;
            const int o  = ((bn0 + wn) >> 4) + (nf >> 1);
            const int k  = ((nf & 1) << 3) + t * 2;
            float* p = Cz + o * (BB * KD) + k;
            *(float2*)&p[r0 * KD] =
                make_float2(acc[mf][nf][0], acc[mf][nf][1]);
            *(float2*)&p[(r0 + 8) * KD] =
                make_float2(acc[mf][nf][2], acc[mf][nf][3]);
        }
}

// ---------------------------------------------------------------------------
// Reduce split-K partials -> bf16 m. Coalesced: float4 reads, uint2 write.
// ---------------------------------------------------------------------------
__global__ __launch_bounds__(256) void reduce_kernel(
    const float* __restrict__ part, __nv_bfloat16* __restrict__ m)
{
    const int idx = blockIdx.x * 256 + threadIdx.x;   // float4 index
    const float4* p = (const float4*)part;
    float4 acc = p[idx];
#pragma unroll
    for (int sp = 1; sp < SPLITS; sp++) {
        float4 v = p[idx + sp * (PSZ / 4)];
        acc.x += v.x; acc.y += v.y; acc.z += v.z; acc.w += v.w;
    }
    __nv_bfloat162 b0 = __floats2bfloat162_rn(acc.x, acc.y);
    __nv_bfloat162 b1 = __floats2bfloat162_rn(acc.z, acc.w);
    uint2 o;
    o.x = *(uint32_t*)&b0; o.y = *(uint32_t*)&b1;
    *(uint2*)&m[(size_t)idx * 4] = o;
}

// ---------------------------------------------------------------------------
// Pairwise exp(-L1) in packed bf16x2: balanced cyclic triangle, 4 t-slices.
// Rows 32 B; fast path = 1 LDS.128 + 7 HADD2 + 4 AND. Negated rows in smem.
// grid (128 o, 4 slice), 256 threads; 32 iters/thread (s3: 31+peel).
// ---------------------------------------------------------------------------
__global__ __launch_bounds__(256) void pair_kernel(
    const __nv_bfloat16* __restrict__ m, float* __restrict__ out)
{
    __shared__ uint4 sm[2][BB];        // [chunk][b], negated bf16 rows, 8 KB

    const int o   = blockIdx.x;
    const int s   = blockIdx.y;
    const int b1  = threadIdx.x;
    const uint32_t SGN = 0x80008000u;
    const uint32_t MSK = 0x7FFF7FFFu;

    // cooperative coalesced load: o-slice = 256 rows x 32 B = 512 chunks
    const uint4* mo = (const uint4*)(m + (size_t)o * (BB * KD));
#pragma unroll
    for (int i = 0; i < 2; i++) {
        const int f = b1 + (i << 8);          // chunk index 0..511
        uint4 v = mo[f];
        v.x ^= SGN; v.y ^= SGN; v.z ^= SGN; v.w ^= SGN;
        sm[f & 1][f >> 1] = v;
    }
    __syncthreads();

    // own (positive) row
    uint32_t a[8];
    {
        uint4 v0 = sm[0][b1], v1 = sm[1][b1];
        a[0] = v0.x ^ SGN; a[1] = v0.y ^ SGN; a[2] = v0.z ^ SGN; a[3] = v0.w ^ SGN;
        a[4] = v1.x ^ SGN; a[5] = v1.y ^ SGN; a[6] = v1.z ^ SGN; a[7] = v1.w ^ SGN;
    }

    float* ob = out + IN_F + o;
    float tot = 0.0f;

    auto body = [&](int t) {
        const int b2 = (b1 + t) & 255;
        uint4 c = sm[0][b2];
        uint32_t d0 = hadd2(a[0], c.x) & MSK;
        uint32_t d1 = hadd2(a[1], c.y) & MSK;
        uint32_t d2 = hadd2(a[2], c.z) & MSK;
        uint32_t d3 = hadd2(a[3], c.w) & MSK;
        uint32_t f  = hadd2(hadd2(d0, d1), hadd2(d2, d3));
        float s8 = __uint_as_float(f << 16) + __uint_as_float(f & 0xFFFF0000u);

        if (s8 < THRESH) {               // else contribution is +0 exactly
            uint4 e = sm[1][b2];
            uint32_t d4 = hadd2(a[4], e.x) & MSK;
            uint32_t d5 = hadd2(a[5], e.y) & MSK;
            uint32_t d6 = hadd2(a[6], e.z) & MSK;
            uint32_t d7 = hadd2(a[7], e.w) & MSK;
            uint32_t g  = hadd2(hadd2(d4, d5), hadd2(d6, d7));
            float s16 = s8 + __uint_as_float(g << 16)
                           + __uint_as_float(g & 0xFFFF0000u);
            float ev = __expf(-s16);
            tot += ev;
            if (ev != 0.0f)              // credit the partner side
                atomicAdd(&ob[(size_t)b2 * OUTW], ev);
        }
    };

    // slices: t = 1+32s .. 32+32s  (s=3: ..127, then peel t=128 once)
    const int t0   = 1 + (s << 5);
    const int tend = (s == QSPLIT - 1) ? 128 : t0 + 32;
#pragma unroll 4
    for (int t = t0; t < tend; t++) body(t);
    if (s == QSPLIT - 1 && b1 < 128) body(128);

    if (tot != 0.0f)
        atomicAdd(&ob[(size_t)b1 * OUTW], tot);
}

extern "C" void kernel_launch(void* const* d_in, const int* in_sizes, int n_in,
                              void* d_out, int out_size)
{
    const float* x = (const float*)d_in[0];     // [256][1024]
    const float* t = (const float*)d_in[1];     // [1024][2048]
    float* out = (float*)d_out;                 // [256][1152]

    float* part;          cudaGetSymbolAddress((void**)&part, d_part);
    __nv_bfloat16* mb;    cudaGetSymbolAddress((void**)&mb, d_mb);
    __nv_bfloat16* tb;    cudaGetSymbolAddress((void**)&tb, d_tb);
    __nv_bfloat16* xb;    cudaGetSymbolAddress((void**)&xb, d_xb);

    conv_kernel<<<1280, 256>>>(t, x, tb, xb, out);
    dim3 ggrid(NCOL / BN, BB / BM, SPLITS);      // (32, 4, 4)
    gemm_bf16_kernel<<<ggrid, 128>>>(xb, tb, part);
    reduce_kernel<<<PSZ / 4 / 256, 256>>>(part, mb);
    pair_kernel<<<dim3(OUT_F, QSPLIT), 256>>>(mb, out);
}

// round 16
// speedup vs baseline: 1.1825x; 1.0965x over previous
#include <cuda_runtime.h>
#include <cuda_bf16.h>
#include <cstdint>

#define BB     256
#define IN_F   1024
#define OUT_F  128
#define KD     16
#define NCOL   (OUT_F * KD)        // 2048
#define OUTW   (IN_F + OUT_F)      // 1152

#define SPLITS 4
#define KSPLIT (IN_F / SPLITS)     // 256
#define PSZ    (BB * NCOL)         // 524288 elems per split partial
#define BM     64
#define BN     64
#define BKK    32
#define NKT    (KSPLIT / BKK)      // 8
#define STAGES 3

#define A_STRIDE 80
#define B_STRIDE 144

#define QSPLIT 4                   // pair t-range slices

// exp(-s) == +0.0f exactly for s >= 105 (underflow cutoff ~104); partial L1
// sums are lower bounds, so screening is lossless.
#define THRESH 105.0f

__device__ __nv_bfloat16 d_pb[SPLITS * PSZ];     // bf16 partials [sp][o][b][k], 4 MB
__device__ __nv_bfloat16 d_tb[IN_F * NCOL];      // t in bf16, 4 MB
__device__ __nv_bfloat16 d_xb[BB * IN_F];        // x in bf16, 0.5 MB

__device__ __forceinline__ void cp16(uint32_t smem, const void* gmem) {
    asm volatile("cp.async.cg.shared.global [%0], [%1], 16;"
                 :: "r"(smem), "l"(gmem));
}

__device__ __forceinline__ uint32_t hadd2(uint32_t a, uint32_t b) {
    uint32_t r;
    asm("add.rn.bf16x2 %0, %1, %2;" : "=r"(r) : "r"(a), "r"(b));
    return r;
}

__device__ __forceinline__ void ldmat4(uint32_t& r0, uint32_t& r1,
                                       uint32_t& r2, uint32_t& r3,
                                       uint32_t addr) {
    asm volatile("ldmatrix.sync.aligned.m8n8.x4.shared.b16 {%0,%1,%2,%3}, [%4];"
                 : "=r"(r0), "=r"(r1), "=r"(r2), "=r"(r3) : "r"(addr));
}
__device__ __forceinline__ void ldmat4t(uint32_t& r0, uint32_t& r1,
                                        uint32_t& r2, uint32_t& r3,
                                        uint32_t addr) {
    asm volatile("ldmatrix.sync.aligned.m8n8.x4.trans.shared.b16 {%0,%1,%2,%3}, [%4];"
                 : "=r"(r0), "=r"(r1), "=r"(r2), "=r"(r3) : "r"(addr));
}

__device__ __forceinline__ uint32_t pack_bf16(float a, float b) {
    __nv_bfloat162 v = __floats2bfloat162_rn(a, b);
    return *(uint32_t*)&v;
}

// ---------------------------------------------------------------------------
// Convert t,x -> bf16 + x passthrough + o_b zero init.
// ---------------------------------------------------------------------------
__global__ __launch_bounds__(256) void conv_kernel(
    const float* __restrict__ t, const float* __restrict__ x,
    __nv_bfloat16* __restrict__ tb, __nv_bfloat16* __restrict__ xb,
    float* __restrict__ out)
{
    const int tid = threadIdx.x;
    const int blk = blockIdx.x;

    if (blk < 1024 + 128) {
        const float*   src = (blk < 1024) ? t : x;
        __nv_bfloat16* dst = (blk < 1024) ? tb : xb;
        const size_t gid = (size_t)(blk < 1024 ? blk : blk - 1024) * 256 + tid;
        const float4* s4 = (const float4*)src;
        float4 v0 = s4[gid * 2];
        float4 v1 = s4[gid * 2 + 1];
        uint4 o;
        o.x = pack_bf16(v0.x, v0.y); o.y = pack_bf16(v0.z, v0.w);
        o.z = pack_bf16(v1.x, v1.y); o.w = pack_bf16(v1.z, v1.w);
        *(uint4*)&dst[gid * 8] = o;
        return;
    }

    const int id = blk - 1152;
    const int r  = id * 2 + (tid >> 7);
    const int j  = tid & 127;
    const float4* src = (const float4*)(x + r * IN_F);
    float4*       dst = (float4*)(out + r * OUTW);
    dst[j]       = src[j];
    dst[j + 128] = src[j + 128];
    if (j < 32)   // diagonal never computed -> 0
        ((float4*)(out + r * OUTW + IN_F))[j] = make_float4(0.f, 0.f, 0.f, 0.f);
}

// ---------------------------------------------------------------------------
// GEMM via mma.sync m16n8k16 bf16: split-K x4, 64x64 tiles, 128 threads,
// ldmatrix, 3-stage cp.async ring. Epilogue writes bf16 partials [sp][o][b][k].
// ---------------------------------------------------------------------------
__global__ __launch_bounds__(128) void gemm_bf16_kernel(
    const __nv_bfloat16* __restrict__ A,
    const __nv_bfloat16* __restrict__ B,
    __nv_bfloat16* __restrict__ Cb)
{
    __shared__ char As[STAGES][BM * A_STRIDE];
    __shared__ char Bs[STAGES][BKK * B_STRIDE];

    const int tid  = threadIdx.x;
    const int lane = tid & 31;
    const int wid  = tid >> 5;
    const int g    = lane >> 2;
    const int t    = lane & 3;
    const int wm   = (wid >> 1) * 32;
    const int wn   = (wid & 1) * 32;
    const int bm0  = blockIdx.y * BM;
    const int bn0  = blockIdx.x * BN;
    const int koff = blockIdx.z * KSPLIT;

    const int lm = lane & 15;
    const int lh = (lane >> 4) & 1;

    const int arow = tid >> 2;
    const int ach  = tid & 3;
    const int brow = tid >> 3;
    const int bch  = tid & 7;

    uint32_t as_b[STAGES], bs_b[STAGES];
#pragma unroll
    for (int b = 0; b < STAGES; b++) {
        as_b[b] = (uint32_t)__cvta_generic_to_shared(&As[b][0]);
        bs_b[b] = (uint32_t)__cvta_generic_to_shared(&Bs[b][0]);
    }

    auto fetch = [&](int buf, int k0) {
#pragma unroll
        for (int i = 0; i < 2; i++) {
            const int r = arow + i * 32;
            cp16(as_b[buf] + r * A_STRIDE + ach * 16,
                 &A[(size_t)(bm0 + r) * IN_F + k0 + ach * 8]);
        }
#pragma unroll
        for (int i = 0; i < 2; i++) {
            const int r = brow + i * 16;
            cp16(bs_b[buf] + r * B_STRIDE + bch * 16,
                 &B[(size_t)(k0 + r) * NCOL + bn0 + bch * 8]);
        }
        asm volatile("cp.async.commit_group;");
    };

    float acc[2][4][4];
#pragma unroll
    for (int mf = 0; mf < 2; mf++)
#pragma unroll
        for (int nf = 0; nf < 4; nf++)
#pragma unroll
            for (int i = 0; i < 4; i++) acc[mf][nf][i] = 0.0f;

    fetch(0, koff);
    fetch(1, koff + BKK);

#pragma unroll 1
    for (int kt = 0; kt < NKT; kt++) {
        if (kt + 1 < NKT) asm volatile("cp.async.wait_group 1;");
        else              asm volatile("cp.async.wait_group 0;");
        __syncthreads();

        if (kt + 2 < NKT) fetch((kt + 2) % STAGES, koff + (kt + 2) * BKK);

        const int cur = kt % STAGES;
#pragma unroll
        for (int ks = 0; ks < 2; ks++) {
            uint32_t ua[2][4], ub[4][2];
#pragma unroll
            for (int mf = 0; mf < 2; mf++) {
                uint32_t addr = as_b[cur] + (wm + mf * 16 + lm) * A_STRIDE
                              + ks * 32 + lh * 16;
                ldmat4(ua[mf][0], ua[mf][1], ua[mf][2], ua[mf][3], addr);
            }
#pragma unroll
            for (int p = 0; p < 2; p++) {
                uint32_t addr = bs_b[cur] + (ks * 16 + lm) * B_STRIDE
                              + (wn + p * 16) * 2 + lh * 16;
                ldmat4t(ub[2 * p][0], ub[2 * p][1],
                        ub[2 * p + 1][0], ub[2 * p + 1][1], addr);
            }
#pragma unroll
            for (int mf = 0; mf < 2; mf++)
#pragma unroll
                for (int nf = 0; nf < 4; nf++) {
                    asm volatile(
                        "mma.sync.aligned.m16n8k16.row.col.f32.bf16.bf16.f32 "
                        "{%0,%1,%2,%3}, {%4,%5,%6,%7}, {%8,%9}, {%0,%1,%2,%3};\n"
                        : "+f"(acc[mf][nf][0]), "+f"(acc[mf][nf][1]),
                          "+f"(acc[mf][nf][2]), "+f"(acc[mf][nf][3])
                        : "r"(ua[mf][0]), "r"(ua[mf][1]),
                          "r"(ua[mf][2]), "r"(ua[mf][3]),
                          "r"(ub[nf][0]), "r"(ub[nf][1]));
                }
        }
    }

    __nv_bfloat16* Cz = Cb + blockIdx.z * PSZ;
#pragma unroll
    for (int mf = 0; mf < 2; mf++)
#pragma unroll
        for (int nf = 0; nf < 4; nf++) {
            const int r0 = bm0 + wm + mf * 16 + g;
            const int o  = ((bn0 + wn) >> 4) + (nf >> 1);
            const int k  = ((nf & 1) << 3) + t * 2;
            __nv_bfloat16* p = Cz + (size_t)o * (BB * KD) + k;
            *(uint32_t*)&p[(size_t)r0 * KD] =
                pack_bf16(acc[mf][nf][0], acc[mf][nf][1]);
            *(uint32_t*)&p[(size_t)(r0 + 8) * KD] =
                pack_bf16(acc[mf][nf][2], acc[mf][nf][3]);
        }
}

// ---------------------------------------------------------------------------
// Pairwise exp(-L1) in packed bf16x2 with FUSED split-K reduction in the
// preamble: coop-load 4 bf16 partial slices, hadd2-sum, negate, stage.
// Balanced cyclic triangle, 4 t-slices. grid (128 o, 4), 256 threads.
// ---------------------------------------------------------------------------
__global__ __launch_bounds__(256) void pair_kernel(
    const __nv_bfloat16* __restrict__ pb, float* __restrict__ out)
{
    __shared__ uint4 sm[2][BB];        // [chunk][b], negated bf16 rows, 8 KB

    const int o   = blockIdx.x;
    const int s   = blockIdx.y;
    const int b1  = threadIdx.x;
    const uint32_t SGN = 0x80008000u;
    const uint32_t MSK = 0x7FFF7FFFu;

    // o-slice = 512 uint4 chunks per split; sum 4 splits, negate, stage
    const uint4* po = (const uint4*)pb;   // PSZ/8 uint4 per split
    const int base = o * 512;
#pragma unroll
    for (int i = 0; i < 2; i++) {
        const int f = b1 + (i << 8);          // chunk index 0..511
        uint4 v = po[base + f];
#pragma unroll
        for (int sp = 1; sp < SPLITS; sp++) {
            uint4 w = po[sp * (PSZ / 8) + base + f];
            v.x = hadd2(v.x, w.x); v.y = hadd2(v.y, w.y);
            v.z = hadd2(v.z, w.z); v.w = hadd2(v.w, w.w);
        }
        v.x ^= SGN; v.y ^= SGN; v.z ^= SGN; v.w ^= SGN;
        sm[f & 1][f >> 1] = v;
    }
    __syncthreads();

    // own (positive) row
    uint32_t a[8];
    {
        uint4 v0 = sm[0][b1], v1 = sm[1][b1];
        a[0] = v0.x ^ SGN; a[1] = v0.y ^ SGN; a[2] = v0.z ^ SGN; a[3] = v0.w ^ SGN;
        a[4] = v1.x ^ SGN; a[5] = v1.y ^ SGN; a[6] = v1.z ^ SGN; a[7] = v1.w ^ SGN;
    }

    float* ob = out + IN_F + o;
    float tot = 0.0f;

    auto body = [&](int t) {
        const int b2 = (b1 + t) & 255;
        uint4 c = sm[0][b2];
        uint32_t d0 = hadd2(a[0], c.x) & MSK;
        uint32_t d1 = hadd2(a[1], c.y) & MSK;
        uint32_t d2 = hadd2(a[2], c.z) & MSK;
        uint32_t d3 = hadd2(a[3], c.w) & MSK;
        uint32_t f  = hadd2(hadd2(d0, d1), hadd2(d2, d3));
        float s8 = __uint_as_float(f << 16) + __uint_as_float(f & 0xFFFF0000u);

        if (s8 < THRESH) {               // else contribution is +0 exactly
            uint4 e = sm[1][b2];
            uint32_t d4 = hadd2(a[4], e.x) & MSK;
            uint32_t d5 = hadd2(a[5], e.y) & MSK;
            uint32_t d6 = hadd2(a[6], e.z) & MSK;
            uint32_t d7 = hadd2(a[7], e.w) & MSK;
            uint32_t g  = hadd2(hadd2(d4, d5), hadd2(d6, d7));
            float s16 = s8 + __uint_as_float(g << 16)
                           + __uint_as_float(g & 0xFFFF0000u);
            float ev = __expf(-s16);
            tot += ev;
            if (ev != 0.0f)              // credit the partner side
                atomicAdd(&ob[(size_t)b2 * OUTW], ev);
        }
    };

    // slices: t = 1+32s .. 32+32s  (s=3: ..127, then peel t=128 once)
    const int t0   = 1 + (s << 5);
    const int tend = (s == QSPLIT - 1) ? 128 : t0 + 32;
#pragma unroll 4
    for (int t = t0; t < tend; t++) body(t);
    if (s == QSPLIT - 1 && b1 < 128) body(128);

    if (tot != 0.0f)
        atomicAdd(&ob[(size_t)b1 * OUTW], tot);
}

extern "C" void kernel_launch(void* const* d_in, const int* in_sizes, int n_in,
                              void* d_out, int out_size)
{
    const float* x = (const float*)d_in[0];     // [256][1024]
    const float* t = (const float*)d_in[1];     // [1024][2048]
    float* out = (float*)d_out;                 // [256][1152]

    __nv_bfloat16* pb;    cudaGetSymbolAddress((void**)&pb, d_pb);
    __nv_bfloat16* tb;    cudaGetSymbolAddress((void**)&tb, d_tb);
    __nv_bfloat16* xb;    cudaGetSymbolAddress((void**)&xb, d_xb);

    conv_kernel<<<1280, 256>>>(t, x, tb, xb, out);
    dim3 ggrid(NCOL / BN, BB / BM, SPLITS);      // (32, 4, 4)
    gemm_bf16_kernel<<<ggrid, 128>>>(xb, tb, pb);
    pair_kernel<<<dim3(OUT_F, QSPLIT), 256>>>(pb, out);
}